// round 9
// baseline (speedup 1.0000x reference)
#include <cuda_runtime.h>
#include <cuda_bf16.h>
#include <math_constants.h>

typedef unsigned int u32;
typedef __nv_bfloat16 bf;

// Problem constants
#define BATCH 8
#define TSEQ  2048
#define CDIM  1024
#define HS    64
#define BT    (BATCH * TSEQ)   // 16384

// Pre-split bf16 hi/lo scratch — __device__ globals per allocation rules.
__device__ bf g_qhi[BT * HS], g_qlo[BT * HS];
__device__ bf g_khi[BT * HS], g_klo[BT * HS];
__device__ bf g_vhi[BT * HS], g_vlo[BT * HS];
__device__ bf g_whi[3 * CDIM * HS], g_wlo[3 * CDIM * HS];   // order Q,K,V

// ---------------- bf16 mma.sync + ldmatrix + cp.async (all baseline PTX) -------
__device__ __forceinline__ void mma16816(float* d, const u32* a, const u32* b) {
    asm volatile(
        "mma.sync.aligned.m16n8k16.row.col.f32.bf16.bf16.f32 "
        "{%0,%1,%2,%3}, {%4,%5,%6,%7}, {%8,%9}, {%0,%1,%2,%3};"
        : "+f"(d[0]), "+f"(d[1]), "+f"(d[2]), "+f"(d[3])
        : "r"(a[0]), "r"(a[1]), "r"(a[2]), "r"(a[3]), "r"(b[0]), "r"(b[1]));
}
__device__ __forceinline__ void ldsm4(u32& r0, u32& r1, u32& r2, u32& r3, u32 addr) {
    asm volatile("ldmatrix.sync.aligned.m8n8.x4.shared.b16 {%0,%1,%2,%3}, [%4];"
                 : "=r"(r0), "=r"(r1), "=r"(r2), "=r"(r3) : "r"(addr));
}
__device__ __forceinline__ void ldsm4t(u32& r0, u32& r1, u32& r2, u32& r3, u32 addr) {
    asm volatile("ldmatrix.sync.aligned.m8n8.x4.trans.shared.b16 {%0,%1,%2,%3}, [%4];"
                 : "=r"(r0), "=r"(r1), "=r"(r2), "=r"(r3) : "r"(addr));
}
__device__ __forceinline__ u32 smem_u32(const void* p) {
    u32 a; asm("{ .reg .u64 t; cvta.to.shared.u64 t, %1; cvt.u32.u64 %0, t; }"
               : "=r"(a) : "l"(p));
    return a;
}
__device__ __forceinline__ void cpa16(u32 dst, const void* src) {
    asm volatile("cp.async.cg.shared.global [%0], [%1], 16;"
                 :: "r"(dst), "l"(__cvta_generic_to_global(src)));
}
__device__ __forceinline__ void cpa_commit() {
    asm volatile("cp.async.commit_group;" ::: "memory");
}
__device__ __forceinline__ void cpa_wait0() {
    asm volatile("cp.async.wait_group 0;" ::: "memory");
}

// Split two fp32 into packed-bf16 hi and lo words (x = hi + lo, ~16 mantissa bits)
__device__ __forceinline__ void split2(float x0, float x1, u32& hi, u32& lo) {
    __nv_bfloat162 h = __floats2bfloat162_rn(x0, x1);
    float r0 = x0 - __bfloat162float(h.x);
    float r1 = x1 - __bfloat162float(h.y);
    __nv_bfloat162 lw = __floats2bfloat162_rn(r0, r1);
    hi = *(u32*)&h;
    lo = *(u32*)&lw;
}

// smem row strides (bf16): ldmatrix conflict-free, rows 16B-aligned.
#define ST  72      // 64 data + 8 pad
#define STB 136     // 128 data + 8 pad

// =============================================================================
// W pre-split: 3 x [1024 x 64] fp32 -> bf16 hi/lo. Tiny, runs once.
// =============================================================================
__global__ __launch_bounds__(256)
void wsplit_kernel(const float* __restrict__ Wq, const float* __restrict__ Wk,
                   const float* __restrict__ Wv)
{
    int base = (blockIdx.x * 256 + threadIdx.x) * 4;   // 192 CTAs cover 196608
#pragma unroll
    for (int e = 0; e < 4; e += 2) {
        int idx = base + e;
        int mat = idx >> 16, rem = idx & 65535;
        const float* W = (mat == 0) ? Wq : (mat == 1) ? Wk : Wv;
        float2 v = *(const float2*)(W + rem);
        u32 hi, lo;
        split2(v.x, v.y, hi, lo);
        *(u32*)(g_whi + idx) = hi;
        *(u32*)(g_wlo + idx) = lo;
    }
}

// =============================================================================
// Projection. Grid 384: bid<128 -> Q path (M=128, N=64, x_q);
// bid>=128 -> KV path (M=64, N=128 = [K|V], x_kv).
// Pipelined: double-buffered smem, cp.async for B, register-staged A (one
// chunk ahead), ONE __syncthreads per chunk. 2 CTAs/SM.
// =============================================================================
#define P_SMEM 110592
#define W_K_OFF (CDIM * HS)
#define W_V_OFF (2 * CDIM * HS)
// Q path offsets: Abuf[c] at c*36864 (hi 18432 + lo 18432); Bbuf[c] at 73728+c*18432
// KV path: Abuf[c] at c*18432 (hi+lo 9216 ea); Bbuf[c] at 36864+c*34816 (hi+lo 17408)

__global__ __launch_bounds__(128, 2)
void proj_kernel(const float* __restrict__ xq, const float* __restrict__ xkv)
{
    extern __shared__ char dsm[];
    const u32 smb = smem_u32(dsm);
    const int tid = threadIdx.x, wid = tid >> 5, l = tid & 31;
    const int g = l >> 2, pp = l & 3;
    const int lr = l & 7, lb8 = (l >> 3) & 1, lb16 = l >> 4;
    const int bid = blockIdx.x;

    if (bid < 128) {
        // ---------------- Q path: M=128, N=64 ----------------
        const int m0 = bid * 128;
        const float* Xp = xq + (size_t)m0 * CDIM;
        const int r_ = tid >> 4, c4_ = tid & 15;   // A-load/store thread map

        float acc[2][8][4];
#pragma unroll
        for (int m = 0; m < 2; m++)
#pragma unroll
            for (int t = 0; t < 8; t++)
#pragma unroll
                for (int i = 0; i < 4; i++) acc[m][t][i] = 0.f;

        float4 ar[16];
        // A chunk 0 -> regs
#pragma unroll
        for (int i = 0; i < 16; i++)
            ar[i] = *(const float4*)(Xp + (size_t)(r_ + 8 * i) * CDIM + c4_ * 4);
        // B chunk 0 -> Bbuf0 via cp.async
        {
            u32 bb = smb + 73728;
#pragma unroll
            for (int i = 0; i < 8; i++) {
                int idx = tid + 128 * i;
                int arr = idx >> 9, rem = idx & 511;
                int k = rem >> 3, seg = rem & 7;
                const bf* src = (arr ? g_wlo : g_whi) + (size_t)k * HS + seg * 8;
                cpa16(bb + arr * 9216 + (k * ST + seg * 8) * 2, src);
            }
            cpa_commit();
        }
        // A chunk 0 regs -> Abuf0 (split)
        {
            char* A0 = dsm;
#pragma unroll
            for (int i = 0; i < 16; i++) {
                int r = r_ + 8 * i;
                u32 h0, l0, h1, l1;
                split2(ar[i].x, ar[i].y, h0, l0); split2(ar[i].z, ar[i].w, h1, l1);
                *(uint2*)(A0 + (r * ST + c4_ * 4) * 2)         = make_uint2(h0, h1);
                *(uint2*)(A0 + 18432 + (r * ST + c4_ * 4) * 2) = make_uint2(l0, l1);
            }
        }
        // A chunk 1 -> regs
#pragma unroll
        for (int i = 0; i < 16; i++)
            ar[i] = *(const float4*)(Xp + (size_t)(r_ + 8 * i) * CDIM + 64 + c4_ * 4);

        for (int ch = 0; ch < 16; ch++) {
            const int cur = ch & 1;
            cpa_wait0();
            __syncthreads();

            if (ch + 1 < 16) {
                // B chunk ch+1 -> other buffer (async)
                u32 bb = smb + 73728 + (cur ^ 1) * 18432;
                const int k0n = (ch + 1) * 64;
#pragma unroll
                for (int i = 0; i < 8; i++) {
                    int idx = tid + 128 * i;
                    int arr = idx >> 9, rem = idx & 511;
                    int k = rem >> 3, seg = rem & 7;
                    const bf* src = (arr ? g_wlo : g_whi) + (size_t)(k0n + k) * HS + seg * 8;
                    cpa16(bb + arr * 9216 + (k * ST + seg * 8) * 2, src);
                }
                cpa_commit();
                // A regs (chunk ch+1) -> other buffer (split)
                char* An = dsm + (cur ^ 1) * 36864;
#pragma unroll
                for (int i = 0; i < 16; i++) {
                    int r = r_ + 8 * i;
                    u32 h0, l0, h1, l1;
                    split2(ar[i].x, ar[i].y, h0, l0); split2(ar[i].z, ar[i].w, h1, l1);
                    *(uint2*)(An + (r * ST + c4_ * 4) * 2)         = make_uint2(h0, h1);
                    *(uint2*)(An + 18432 + (r * ST + c4_ * 4) * 2) = make_uint2(l0, l1);
                }
                if (ch + 2 < 16) {
                    const int k0nn = (ch + 2) * 64;
#pragma unroll
                    for (int i = 0; i < 16; i++)
                        ar[i] = *(const float4*)(Xp + (size_t)(r_ + 8 * i) * CDIM
                                                 + k0nn + c4_ * 4);
                }
            }

            // ---- MMA on current buffers ----
            const u32 sAhi = smb + cur * 36864, sAlo = sAhi + 18432;
            const u32 sBhi = smb + 73728 + cur * 18432, sBlo = sBhi + 9216;
#pragma unroll
            for (int k16 = 0; k16 < 4; k16++) {
                u32 ah[2][4], al[2][4];
#pragma unroll
                for (int m = 0; m < 2; m++) {
                    u32 off = (u32)(((wid * 32 + m * 16 + lr + lb8 * 8) * ST
                                   + k16 * 16 + lb16 * 8) * 2);
                    ldsm4(ah[m][0], ah[m][1], ah[m][2], ah[m][3], sAhi + off);
                    ldsm4(al[m][0], al[m][1], al[m][2], al[m][3], sAlo + off);
                }
#pragma unroll
                for (int tp = 0; tp < 4; tp++) {
                    u32 boff = (u32)(((k16 * 16 + lr + lb8 * 8) * ST
                                    + tp * 16 + lb16 * 8) * 2);
                    u32 bh[4], bl[4];
                    ldsm4t(bh[0], bh[1], bh[2], bh[3], sBhi + boff);
                    ldsm4t(bl[0], bl[1], bl[2], bl[3], sBlo + boff);
#pragma unroll
                    for (int m = 0; m < 2; m++) {
                        mma16816(acc[m][2 * tp],     ah[m], bh);
                        mma16816(acc[m][2 * tp],     al[m], bh);
                        mma16816(acc[m][2 * tp],     ah[m], bl);
                        mma16816(acc[m][2 * tp + 1], ah[m], bh + 2);
                        mma16816(acc[m][2 * tp + 1], al[m], bh + 2);
                        mma16816(acc[m][2 * tp + 1], ah[m], bl + 2);
                    }
                }
            }
        }
        // epilogue: split fp32 accs -> g_qhi/g_qlo
#pragma unroll
        for (int m = 0; m < 2; m++)
#pragma unroll
            for (int t = 0; t < 8; t++) {
                int row = m0 + wid * 32 + m * 16 + g;
                int col = t * 8 + pp * 2;
                u32 hi, lo;
                split2(acc[m][t][0], acc[m][t][1], hi, lo);
                *(u32*)(g_qhi + (size_t)row * HS + col) = hi;
                *(u32*)(g_qlo + (size_t)row * HS + col) = lo;
                split2(acc[m][t][2], acc[m][t][3], hi, lo);
                *(u32*)(g_qhi + (size_t)(row + 8) * HS + col) = hi;
                *(u32*)(g_qlo + (size_t)(row + 8) * HS + col) = lo;
            }
    } else {
        // ---------------- KV path: M=64, N=128 ([K|V]) ----------------
        const int m0 = (bid - 128) * 64;
        const float* Xp = xkv + (size_t)m0 * CDIM;
        const int r_ = tid >> 4, c4_ = tid & 15;

        float acc[16][4];
#pragma unroll
        for (int t = 0; t < 16; t++)
#pragma unroll
            for (int i = 0; i < 4; i++) acc[t][i] = 0.f;

        float4 ar[8];
#pragma unroll
        for (int i = 0; i < 8; i++)
            ar[i] = *(const float4*)(Xp + (size_t)(r_ + 8 * i) * CDIM + c4_ * 4);
        {
            u32 bb = smb + 36864;
#pragma unroll
            for (int i = 0; i < 16; i++) {
                int idx = tid + 128 * i;
                int arr = idx >> 10, rem = idx & 1023;
                int k = rem >> 4, seg = rem & 15;
                size_t woff = (seg < 8)
                    ? (W_K_OFF + (size_t)k * HS + seg * 8)
                    : (W_V_OFF + (size_t)k * HS + (seg - 8) * 8);
                cpa16(bb + arr * 17408 + (k * STB + seg * 8) * 2,
                      (arr ? g_wlo : g_whi) + woff);
            }
            cpa_commit();
        }
        {
            char* A0 = dsm;
#pragma unroll
            for (int i = 0; i < 8; i++) {
                int r = r_ + 8 * i;
                u32 h0, l0, h1, l1;
                split2(ar[i].x, ar[i].y, h0, l0); split2(ar[i].z, ar[i].w, h1, l1);
                *(uint2*)(A0 + (r * ST + c4_ * 4) * 2)        = make_uint2(h0, h1);
                *(uint2*)(A0 + 9216 + (r * ST + c4_ * 4) * 2) = make_uint2(l0, l1);
            }
        }
#pragma unroll
        for (int i = 0; i < 8; i++)
            ar[i] = *(const float4*)(Xp + (size_t)(r_ + 8 * i) * CDIM + 64 + c4_ * 4);

        for (int ch = 0; ch < 16; ch++) {
            const int cur = ch & 1;
            cpa_wait0();
            __syncthreads();

            if (ch + 1 < 16) {
                u32 bb = smb + 36864 + (cur ^ 1) * 34816;
                const int k0n = (ch + 1) * 64;
#pragma unroll
                for (int i = 0; i < 16; i++) {
                    int idx = tid + 128 * i;
                    int arr = idx >> 10, rem = idx & 1023;
                    int k = rem >> 4, seg = rem & 15;
                    size_t woff = (seg < 8)
                        ? (W_K_OFF + (size_t)(k0n + k) * HS + seg * 8)
                        : (W_V_OFF + (size_t)(k0n + k) * HS + (seg - 8) * 8);
                    cpa16(bb + arr * 17408 + (k * STB + seg * 8) * 2,
                          (arr ? g_wlo : g_whi) + woff);
                }
                cpa_commit();
                char* An = dsm + (cur ^ 1) * 18432;
#pragma unroll
                for (int i = 0; i < 8; i++) {
                    int r = r_ + 8 * i;
                    u32 h0, l0, h1, l1;
                    split2(ar[i].x, ar[i].y, h0, l0); split2(ar[i].z, ar[i].w, h1, l1);
                    *(uint2*)(An + (r * ST + c4_ * 4) * 2)        = make_uint2(h0, h1);
                    *(uint2*)(An + 9216 + (r * ST + c4_ * 4) * 2) = make_uint2(l0, l1);
                }
                if (ch + 2 < 16) {
                    const int k0nn = (ch + 2) * 64;
#pragma unroll
                    for (int i = 0; i < 8; i++)
                        ar[i] = *(const float4*)(Xp + (size_t)(r_ + 8 * i) * CDIM
                                                 + k0nn + c4_ * 4);
                }
            }

            const u32 sAhi = smb + cur * 18432, sAlo = sAhi + 9216;
            const u32 sBhi = smb + 36864 + cur * 34816, sBlo = sBhi + 17408;
#pragma unroll
            for (int k16 = 0; k16 < 4; k16++) {
                u32 ah[4], al[4];
                u32 aoff = (u32)(((wid * 16 + lr + lb8 * 8) * ST
                                + k16 * 16 + lb16 * 8) * 2);
                ldsm4(ah[0], ah[1], ah[2], ah[3], sAhi + aoff);
                ldsm4(al[0], al[1], al[2], al[3], sAlo + aoff);
#pragma unroll
                for (int tp = 0; tp < 8; tp++) {
                    u32 boff = (u32)(((k16 * 16 + lr + lb8 * 8) * STB
                                    + tp * 16 + lb16 * 8) * 2);
                    u32 bh[4], bl[4];
                    ldsm4t(bh[0], bh[1], bh[2], bh[3], sBhi + boff);
                    ldsm4t(bl[0], bl[1], bl[2], bl[3], sBlo + boff);
                    mma16816(acc[2 * tp],     ah, bh);
                    mma16816(acc[2 * tp],     al, bh);
                    mma16816(acc[2 * tp],     ah, bl);
                    mma16816(acc[2 * tp + 1], ah, bh + 2);
                    mma16816(acc[2 * tp + 1], al, bh + 2);
                    mma16816(acc[2 * tp + 1], ah, bl + 2);
                }
            }
        }
        // epilogue: t<8 -> K, t>=8 -> V
#pragma unroll
        for (int t = 0; t < 16; t++) {
            int row = m0 + wid * 16 + g;
            int col = (t & 7) * 8 + pp * 2;
            bf* Dhi = (t < 8) ? g_khi : g_vhi;
            bf* Dlo = (t < 8) ? g_klo : g_vlo;
            u32 hi, lo;
            split2(acc[t][0], acc[t][1], hi, lo);
            *(u32*)(Dhi + (size_t)row * HS + col) = hi;
            *(u32*)(Dlo + (size_t)row * HS + col) = lo;
            split2(acc[t][2], acc[t][3], hi, lo);
            *(u32*)(Dhi + (size_t)(row + 8) * HS + col) = hi;
            *(u32*)(Dlo + (size_t)(row + 8) * HS + col) = lo;
        }
    }
}

// =============================================================================
// Flash attention: one 64-row q-tile per CTA, 256 CTAs, 128 threads, 2 CTAs/SM.
// K/V double-buffered via cp.async — ONE barrier per k-iteration.
// Balanced bid->(qt,batch): co-resident pairs (bid, bid+148) sum to 28;
// the 40 solo SMs get the heaviest tiles (qt 27..31).
// =============================================================================
#define A_QHI 0
#define A_QLO 9216
#define A_KV0 18432         // per-buffer: khi +0, klo +9216, vhi +18432, vlo +27648
#define A_KVSZ 36864
#define A_PHI 92160
#define A_PLO 101376
#define A_SMEM 110592

__global__ __launch_bounds__(128, 2)
void attn_kernel(float* __restrict__ out)
{
    extern __shared__ char dsm[];
    const u32 smb = smem_u32(dsm);
    bf* Qhi = (bf*)(dsm + A_QHI); bf* Qlo = (bf*)(dsm + A_QLO);
    bf* Phi = (bf*)(dsm + A_PHI); bf* Plo = (bf*)(dsm + A_PLO);
    const u32 sQhi = smb + A_QHI, sQlo = smb + A_QLO;
    const u32 sPhi = smb + A_PHI, sPlo = smb + A_PLO;

    const int tid = threadIdx.x, wid = tid >> 5, l = tid & 31;
    const int g = l >> 2, pp = l & 3;
    const int lr = l & 7, lb8 = (l >> 3) & 1, lb16 = l >> 4;

    // --- balanced bid -> (qt, batch) mapping ---
    int bid = blockIdx.x, qt, b;
    if (bid >= 108 && bid < 148) {
        int i = bid - 108;               // 40 solo-heavy tiles: qt 31..27
        qt = 31 - (i >> 3); b = i & 7;
    } else {
        int p = (bid < 108) ? bid : (bid - 148);
        bool second = (bid >= 148);
        if (p < 104) { int j = p >> 3; b = p & 7; qt = second ? (26 - j) : j; }
        else         { int q = p - 104; qt = 13; b = second ? (2 * q + 1) : (2 * q); }
    }
    const int q0 = qt * 64;

    const bf* QgH = g_qhi + (size_t)b * TSEQ * HS;
    const bf* QgL = g_qlo + (size_t)b * TSEQ * HS;
    const bf* KgH = g_khi + (size_t)b * TSEQ * HS;
    const bf* KgL = g_klo + (size_t)b * TSEQ * HS;
    const bf* VgH = g_vhi + (size_t)b * TSEQ * HS;
    const bf* VgL = g_vlo + (size_t)b * TSEQ * HS;

    // Q tile: straight bf16 copy (8 uint4 / thread)
#pragma unroll
    for (int i = 0; i < 8; i++) {
        int idx = tid + 128 * i;
        int arr = idx >> 9, rem = idx & 511;
        int r = rem >> 3, seg = rem & 7;
        const bf* src = (arr ? QgL : QgH) + (size_t)(q0 + r) * HS + seg * 8;
        bf* dst = (arr ? Qlo : Qhi) + r * ST + seg * 8;
        *(uint4*)dst = *(const uint4*)src;
    }
    // prologue: cp.async K/V for kt=0 into buffer 0
#pragma unroll
    for (int i = 0; i < 16; i++) {
        int idx = tid + 128 * i;
        int arr = idx >> 9, rem = idx & 511;
        int r = rem >> 3, seg = rem & 7;
        const bf* src = (arr == 0 ? KgH : arr == 1 ? KgL : arr == 2 ? VgH : VgL)
                      + (size_t)r * HS + seg * 8;
        cpa16(smb + A_KV0 + arr * 9216 + (r * ST + seg * 8) * 2, src);
    }
    cpa_commit();
    __syncthreads();

    // hoist Q a-frags
    u32 qh[4][4], ql[4][4];
#pragma unroll
    for (int k16 = 0; k16 < 4; k16++) {
        u32 off = (u32)(((wid * 16 + lr + lb8 * 8) * ST + k16 * 16 + lb16 * 8) * 2);
        ldsm4(qh[k16][0], qh[k16][1], qh[k16][2], qh[k16][3], sQhi + off);
        ldsm4(ql[k16][0], ql[k16][1], ql[k16][2], ql[k16][3], sQlo + off);
    }

    float o[8][4];
#pragma unroll
    for (int t = 0; t < 8; t++)
#pragma unroll
        for (int i = 0; i < 4; i++) o[t][i] = 0.f;
    float mrow[2] = {-1e30f, -1e30f};
    float lrow[2] = {0.f, 0.f};

    for (int kt = 0; kt <= qt; kt++) {
        const int cur = kt & 1;
        cpa_wait0();
        __syncthreads();   // K/V(kt) visible; all warps done with buffer cur^1

        if (kt < qt) {
            const int k0n = (kt + 1) * 64;
            const u32 dst0 = smb + A_KV0 + (cur ^ 1) * A_KVSZ;
#pragma unroll
            for (int i = 0; i < 16; i++) {
                int idx = tid + 128 * i;
                int arr = idx >> 9, rem = idx & 511;
                int r = rem >> 3, seg = rem & 7;
                const bf* src = (arr == 0 ? KgH : arr == 1 ? KgL : arr == 2 ? VgH : VgL)
                              + (size_t)(k0n + r) * HS + seg * 8;
                cpa16(dst0 + arr * 9216 + (r * ST + seg * 8) * 2, src);
            }
            cpa_commit();
        }

        const u32 base = smb + A_KV0 + cur * A_KVSZ;
        const u32 sKhi = base, sKlo = base + 9216;
        const u32 sVhi = base + 18432, sVlo = base + 27648;
        const int k0 = kt * 64;

        // ---- GEMM1: S = Q K^T ----
        float s[8][4];
#pragma unroll
        for (int t = 0; t < 8; t++)
#pragma unroll
            for (int i = 0; i < 4; i++) s[t][i] = 0.f;
#pragma unroll
        for (int k16 = 0; k16 < 4; k16++) {
#pragma unroll
            for (int tp = 0; tp < 4; tp++) {
                u32 off = (u32)(((16 * tp + lr + lb16 * 8) * ST + k16 * 16 + lb8 * 8) * 2);
                u32 bh[4], bl[4];
                ldsm4(bh[0], bh[1], bh[2], bh[3], sKhi + off);
                ldsm4(bl[0], bl[1], bl[2], bl[3], sKlo + off);
                mma16816(s[2 * tp],     qh[k16], bh);
                mma16816(s[2 * tp],     ql[k16], bh);
                mma16816(s[2 * tp],     qh[k16], bl);
                mma16816(s[2 * tp + 1], qh[k16], bh + 2);
                mma16816(s[2 * tp + 1], ql[k16], bh + 2);
                mma16816(s[2 * tp + 1], qh[k16], bl + 2);
            }
        }

        // ---- scale + causal mask ----
#pragma unroll
        for (int t = 0; t < 8; t++)
#pragma unroll
            for (int i = 0; i < 4; i++) s[t][i] *= 0.03125f;   // 1024^-0.5
        if (kt == qt) {
            const int r0 = q0 + wid * 16 + g, r1 = r0 + 8;
#pragma unroll
            for (int t = 0; t < 8; t++) {
                int c0 = k0 + t * 8 + pp * 2;
                if (c0 > r0)     s[t][0] = -1e30f;
                if (c0 + 1 > r0) s[t][1] = -1e30f;
                if (c0 > r1)     s[t][2] = -1e30f;
                if (c0 + 1 > r1) s[t][3] = -1e30f;
            }
        }

        // ---- online softmax ----
        float rmx[2] = {-1e30f, -1e30f};
#pragma unroll
        for (int t = 0; t < 8; t++) {
            rmx[0] = fmaxf(rmx[0], fmaxf(s[t][0], s[t][1]));
            rmx[1] = fmaxf(rmx[1], fmaxf(s[t][2], s[t][3]));
        }
        float scl[2], rs[2] = {0.f, 0.f};
#pragma unroll
        for (int r = 0; r < 2; r++) {
            rmx[r] = fmaxf(rmx[r], __shfl_xor_sync(0xffffffffu, rmx[r], 1));
            rmx[r] = fmaxf(rmx[r], __shfl_xor_sync(0xffffffffu, rmx[r], 2));
            float mn = fmaxf(mrow[r], rmx[r]);
            scl[r] = __expf(mrow[r] - mn);
            mrow[r] = mn;
        }
#pragma unroll
        for (int t = 0; t < 8; t++) {
            float p00 = __expf(s[t][0] - mrow[0]);
            float p01 = __expf(s[t][1] - mrow[0]);
            float p10 = __expf(s[t][2] - mrow[1]);
            float p11 = __expf(s[t][3] - mrow[1]);
            rs[0] += p00 + p01;
            rs[1] += p10 + p11;
            u32 hi, lo;
            split2(p00, p01, hi, lo);
            *(u32*)(Phi + (wid * 16 + g) * ST + t * 8 + pp * 2) = hi;
            *(u32*)(Plo + (wid * 16 + g) * ST + t * 8 + pp * 2) = lo;
            split2(p10, p11, hi, lo);
            *(u32*)(Phi + (wid * 16 + g + 8) * ST + t * 8 + pp * 2) = hi;
            *(u32*)(Plo + (wid * 16 + g + 8) * ST + t * 8 + pp * 2) = lo;
        }
#pragma unroll
        for (int r = 0; r < 2; r++) {
            rs[r] += __shfl_xor_sync(0xffffffffu, rs[r], 1);
            rs[r] += __shfl_xor_sync(0xffffffffu, rs[r], 2);
            lrow[r] = lrow[r] * scl[r] + rs[r];
        }
#pragma unroll
        for (int t = 0; t < 8; t++) {
            o[t][0] *= scl[0]; o[t][1] *= scl[0];
            o[t][2] *= scl[1]; o[t][3] *= scl[1];
        }
        __syncwarp();   // P writes are warp-local (rows wid*16..wid*16+15)

        // ---- GEMM2: O += P V  (V b-frags via ldmatrix.trans on [s][h]) ----
#pragma unroll
        for (int c16 = 0; c16 < 4; c16++) {
            u32 aoff = (u32)(((wid * 16 + lr + lb8 * 8) * ST + c16 * 16 + lb16 * 8) * 2);
            u32 ph[4], pl[4];
            ldsm4(ph[0], ph[1], ph[2], ph[3], sPhi + aoff);
            ldsm4(pl[0], pl[1], pl[2], pl[3], sPlo + aoff);
#pragma unroll
            for (int tp = 0; tp < 4; tp++) {
                u32 voff = (u32)(((c16 * 16 + lr + lb8 * 8) * ST + 16 * tp + lb16 * 8) * 2);
                u32 vh[4], vl[4];
                ldsm4t(vh[0], vh[1], vh[2], vh[3], sVhi + voff);
                ldsm4t(vl[0], vl[1], vl[2], vl[3], sVlo + voff);
                mma16816(o[2 * tp],     ph, vh);
                mma16816(o[2 * tp],     pl, vh);
                mma16816(o[2 * tp],     ph, vl);
                mma16816(o[2 * tp + 1], ph, vh + 2);
                mma16816(o[2 * tp + 1], pl, vh + 2);
                mma16816(o[2 * tp + 1], ph, vl + 2);
            }
        }
    } // kt

    // ---- epilogue ----
    const float inv0 = 1.f / lrow[0], inv1 = 1.f / lrow[1];
    float* Og = out + ((size_t)b * TSEQ + q0) * HS;
#pragma unroll
    for (int t = 0; t < 8; t++) {
        int row = wid * 16 + g, col = t * 8 + pp * 2;
        *(float2*)(Og + (size_t)row * HS + col) =
            make_float2(o[t][0] * inv0, o[t][1] * inv0);
        *(float2*)(Og + (size_t)(row + 8) * HS + col) =
            make_float2(o[t][2] * inv1, o[t][3] * inv1);
    }
}

// =============================================================================
extern "C" void kernel_launch(void* const* d_in, const int* in_sizes, int n_in,
                              void* d_out, int out_size)
{
    const float* xq  = (const float*)d_in[0];
    const float* xkv = (const float*)d_in[1];
    const float* Wq  = (const float*)d_in[2];
    const float* Wk  = (const float*)d_in[3];
    const float* Wv  = (const float*)d_in[4];
    float* out = (float*)d_out;

    cudaFuncSetAttribute(proj_kernel, cudaFuncAttributeMaxDynamicSharedMemorySize, P_SMEM);
    cudaFuncSetAttribute(attn_kernel, cudaFuncAttributeMaxDynamicSharedMemorySize, A_SMEM);

    wsplit_kernel<<<192, 256>>>(Wq, Wk, Wv);
    proj_kernel<<<384, 128, P_SMEM>>>(xq, xkv);
    attn_kernel<<<256, 128, A_SMEM>>>(out);
}

// round 16
// speedup vs baseline: 1.4397x; 1.4397x over previous
#include <cuda_runtime.h>
#include <cuda_fp16.h>
#include <math_constants.h>

typedef unsigned int u32;
typedef __half hf;

// Problem constants
#define BATCH 8
#define TSEQ  2048
#define CDIM  1024
#define HS    64
#define BT    (BATCH * TSEQ)   // 16384

// Pre-split fp16 scratch — __device__ globals per allocation rules.
// A-side operands keep hi+lo; B-side operands (W, K, V) keep hi only.
__device__ hf g_qhi[BT * HS], g_qlo[BT * HS];
__device__ hf g_khi[BT * HS];
__device__ hf g_vhi[BT * HS];
__device__ hf g_whi[3 * CDIM * HS];   // order Q,K,V

// ---------------- fp16 mma.sync + ldmatrix + cp.async (all baseline PTX) -------
__device__ __forceinline__ void mma16816(float* d, const u32* a, const u32* b) {
    asm volatile(
        "mma.sync.aligned.m16n8k16.row.col.f32.f16.f16.f32 "
        "{%0,%1,%2,%3}, {%4,%5,%6,%7}, {%8,%9}, {%0,%1,%2,%3};"
        : "+f"(d[0]), "+f"(d[1]), "+f"(d[2]), "+f"(d[3])
        : "r"(a[0]), "r"(a[1]), "r"(a[2]), "r"(a[3]), "r"(b[0]), "r"(b[1]));
}
__device__ __forceinline__ void ldsm4(u32& r0, u32& r1, u32& r2, u32& r3, u32 addr) {
    asm volatile("ldmatrix.sync.aligned.m8n8.x4.shared.b16 {%0,%1,%2,%3}, [%4];"
                 : "=r"(r0), "=r"(r1), "=r"(r2), "=r"(r3) : "r"(addr));
}
__device__ __forceinline__ void ldsm4t(u32& r0, u32& r1, u32& r2, u32& r3, u32 addr) {
    asm volatile("ldmatrix.sync.aligned.m8n8.x4.trans.shared.b16 {%0,%1,%2,%3}, [%4];"
                 : "=r"(r0), "=r"(r1), "=r"(r2), "=r"(r3) : "r"(addr));
}
__device__ __forceinline__ u32 smem_u32(const void* p) {
    u32 a; asm("{ .reg .u64 t; cvta.to.shared.u64 t, %1; cvt.u32.u64 %0, t; }"
               : "=r"(a) : "l"(p));
    return a;
}
__device__ __forceinline__ void cpa16(u32 dst, const void* src) {
    asm volatile("cp.async.cg.shared.global [%0], [%1], 16;"
                 :: "r"(dst), "l"(__cvta_generic_to_global(src)));
}
__device__ __forceinline__ void cpa_commit() {
    asm volatile("cp.async.commit_group;" ::: "memory");
}
__device__ __forceinline__ void cpa_wait0() {
    asm volatile("cp.async.wait_group 0;" ::: "memory");
}

// Split two fp32 into packed-fp16 hi and lo words (x = hi + lo, ~22 mantissa bits)
__device__ __forceinline__ void split2(float x0, float x1, u32& hi, u32& lo) {
    __half2 h = __floats2half2_rn(x0, x1);
    float2 hf2 = __half22float2(h);
    __half2 lw = __floats2half2_rn(x0 - hf2.x, x1 - hf2.y);
    hi = *(u32*)&h;
    lo = *(u32*)&lw;
}
__device__ __forceinline__ u32 cvt2(float x0, float x1) {
    __half2 h = __floats2half2_rn(x0, x1);
    return *(u32*)&h;
}

// smem row strides (fp16): ldmatrix conflict-free, rows 16B-aligned.
#define ST  72      // 64 data + 8 pad
#define STB 136     // 128 data + 8 pad

// =============================================================================
// W convert: 3 x [1024 x 64] fp32 -> fp16 (hi only). Tiny, runs once.
// =============================================================================
__global__ __launch_bounds__(256)
void wsplit_kernel(const float* __restrict__ Wq, const float* __restrict__ Wk,
                   const float* __restrict__ Wv)
{
    int base = (blockIdx.x * 256 + threadIdx.x) * 4;   // 192 CTAs cover 196608
#pragma unroll
    for (int e = 0; e < 4; e += 2) {
        int idx = base + e;
        int mat = idx >> 16, rem = idx & 65535;
        const float* W = (mat == 0) ? Wq : (mat == 1) ? Wk : Wv;
        float2 v = *(const float2*)(W + rem);
        *(u32*)(g_whi + idx) = cvt2(v.x, v.y);
    }
}

// =============================================================================
// Projection. Grid 384: bid<128 -> Q path (M=128, N=64, x_q);
// bid>=128 -> KV path (M=64, N=128 = [K|V], x_kv).
// Single-buffer, A register-prefetched one chunk ahead, 3 CTAs/SM.
// 2-pass fp16: (x_hi + x_lo) * w_hi.
// fp16 smem layout (FIXED from R13's OOB offsets):
//   Q path:  Ahi@0 (18432), Alo@18432 (18432), Bhi@36864 (9216)   = 46080
//   KV path: Ahi@0 (9216),  Alo@9216 (9216),  Bhi@18432 (17408)   = 35840
// =============================================================================
#define P_SMEM 46080
#define W_K_OFF (CDIM * HS)
#define W_V_OFF (2 * CDIM * HS)

__global__ __launch_bounds__(128, 3)
void proj_kernel(const float* __restrict__ xq, const float* __restrict__ xkv)
{
    extern __shared__ char dsm[];
    const u32 smb = smem_u32(dsm);
    const int tid = threadIdx.x, wid = tid >> 5, l = tid & 31;
    const int g = l >> 2, pp = l & 3;
    const int lr = l & 7, lb8 = (l >> 3) & 1, lb16 = l >> 4;
    const int bid = blockIdx.x;
    const int r_ = tid >> 4, c4_ = tid & 15;

    if (bid < 128) {
        // ---------------- Q path: M=128, N=64 ----------------
        const int m0 = bid * 128;
        const float* Xp = xq + (size_t)m0 * CDIM;

        float acc[2][8][4];
#pragma unroll
        for (int m = 0; m < 2; m++)
#pragma unroll
            for (int t = 0; t < 8; t++)
#pragma unroll
                for (int i = 0; i < 4; i++) acc[m][t][i] = 0.f;

        float4 ar[16];
#pragma unroll
        for (int i = 0; i < 16; i++)
            ar[i] = *(const float4*)(Xp + (size_t)(r_ + 8 * i) * CDIM + c4_ * 4);

        for (int ch = 0; ch < 16; ch++) {
            const int k0 = ch * 64;
            __syncthreads();   // previous MMA done reading smem
            // A: split prefetched regs -> smem (Ahi@0, Alo@18432)
#pragma unroll
            for (int i = 0; i < 16; i++) {
                int r = r_ + 8 * i;
                u32 h0, l0, h1, l1;
                split2(ar[i].x, ar[i].y, h0, l0); split2(ar[i].z, ar[i].w, h1, l1);
                *(uint2*)(dsm + (r * ST + c4_ * 4) * 2)         = make_uint2(h0, h1);
                *(uint2*)(dsm + 18432 + (r * ST + c4_ * 4) * 2) = make_uint2(l0, l1);
            }
            // B: w_hi straight uint4 copy (4 / thread) -> Bhi@36864
#pragma unroll
            for (int i = 0; i < 4; i++) {
                int idx = tid + 128 * i;
                int k = idx >> 3, seg = idx & 7;
                *(uint4*)(dsm + 36864 + (k * ST + seg * 8) * 2) =
                    *(const uint4*)(g_whi + (size_t)(k0 + k) * HS + seg * 8);
            }
            __syncthreads();
            // prefetch next A chunk (overlaps MMA below)
            if (ch + 1 < 16) {
                const int k0n = (ch + 1) * 64;
#pragma unroll
                for (int i = 0; i < 16; i++)
                    ar[i] = *(const float4*)(Xp + (size_t)(r_ + 8 * i) * CDIM
                                             + k0n + c4_ * 4);
            }

            const u32 sAhi = smb, sAlo = smb + 18432, sBhi = smb + 36864;
#pragma unroll
            for (int k16 = 0; k16 < 4; k16++) {
                u32 ah[2][4], al[2][4];
#pragma unroll
                for (int m = 0; m < 2; m++) {
                    u32 off = (u32)(((wid * 32 + m * 16 + lr + lb8 * 8) * ST
                                   + k16 * 16 + lb16 * 8) * 2);
                    ldsm4(ah[m][0], ah[m][1], ah[m][2], ah[m][3], sAhi + off);
                    ldsm4(al[m][0], al[m][1], al[m][2], al[m][3], sAlo + off);
                }
#pragma unroll
                for (int tp = 0; tp < 4; tp++) {
                    u32 boff = (u32)(((k16 * 16 + lr + lb8 * 8) * ST
                                    + tp * 16 + lb16 * 8) * 2);
                    u32 bh[4];
                    ldsm4t(bh[0], bh[1], bh[2], bh[3], sBhi + boff);
#pragma unroll
                    for (int m = 0; m < 2; m++) {
                        mma16816(acc[m][2 * tp],     ah[m], bh);
                        mma16816(acc[m][2 * tp],     al[m], bh);
                        mma16816(acc[m][2 * tp + 1], ah[m], bh + 2);
                        mma16816(acc[m][2 * tp + 1], al[m], bh + 2);
                    }
                }
            }
        }
        // epilogue: split fp32 accs -> g_qhi/g_qlo
#pragma unroll
        for (int m = 0; m < 2; m++)
#pragma unroll
            for (int t = 0; t < 8; t++) {
                int row = m0 + wid * 32 + m * 16 + g;
                int col = t * 8 + pp * 2;
                u32 hi, lo;
                split2(acc[m][t][0], acc[m][t][1], hi, lo);
                *(u32*)(g_qhi + (size_t)row * HS + col) = hi;
                *(u32*)(g_qlo + (size_t)row * HS + col) = lo;
                split2(acc[m][t][2], acc[m][t][3], hi, lo);
                *(u32*)(g_qhi + (size_t)(row + 8) * HS + col) = hi;
                *(u32*)(g_qlo + (size_t)(row + 8) * HS + col) = lo;
            }
    } else {
        // ---------------- KV path: M=64, N=128 ([K|V]) ----------------
        const int m0 = (bid - 128) * 64;
        const float* Xp = xkv + (size_t)m0 * CDIM;

        float acc[16][4];
#pragma unroll
        for (int t = 0; t < 16; t++)
#pragma unroll
            for (int i = 0; i < 4; i++) acc[t][i] = 0.f;

        float4 ar[8];
#pragma unroll
        for (int i = 0; i < 8; i++)
            ar[i] = *(const float4*)(Xp + (size_t)(r_ + 8 * i) * CDIM + c4_ * 4);

        for (int ch = 0; ch < 16; ch++) {
            const int k0 = ch * 64;
            __syncthreads();
            // A: split prefetched regs -> smem (Ahi@0, Alo@9216)
#pragma unroll
            for (int i = 0; i < 8; i++) {
                int r = r_ + 8 * i;
                u32 h0, l0, h1, l1;
                split2(ar[i].x, ar[i].y, h0, l0); split2(ar[i].z, ar[i].w, h1, l1);
                *(uint2*)(dsm + (r * ST + c4_ * 4) * 2)        = make_uint2(h0, h1);
                *(uint2*)(dsm + 9216 + (r * ST + c4_ * 4) * 2) = make_uint2(l0, l1);
            }
            // B: [k][0..63]=Wk_hi, [k][64..127]=Wv_hi (8 uint4 / thread) -> Bhi@18432
#pragma unroll
            for (int i = 0; i < 8; i++) {
                int idx = tid + 128 * i;
                int k = idx >> 4, seg = idx & 15;
                size_t woff = (seg < 8)
                    ? (W_K_OFF + (size_t)(k0 + k) * HS + seg * 8)
                    : (W_V_OFF + (size_t)(k0 + k) * HS + (seg - 8) * 8);
                *(uint4*)(dsm + 18432 + (k * STB + seg * 8) * 2) =
                    *(const uint4*)(g_whi + woff);
            }
            __syncthreads();
            if (ch + 1 < 16) {
                const int k0n = (ch + 1) * 64;
#pragma unroll
                for (int i = 0; i < 8; i++)
                    ar[i] = *(const float4*)(Xp + (size_t)(r_ + 8 * i) * CDIM
                                             + k0n + c4_ * 4);
            }

            const u32 sAhi = smb, sAlo = smb + 9216, sBhi = smb + 18432;
#pragma unroll
            for (int k16 = 0; k16 < 4; k16++) {
                u32 ah[4], al[4];
                u32 aoff = (u32)(((wid * 16 + lr + lb8 * 8) * ST
                                + k16 * 16 + lb16 * 8) * 2);
                ldsm4(ah[0], ah[1], ah[2], ah[3], sAhi + aoff);
                ldsm4(al[0], al[1], al[2], al[3], sAlo + aoff);
#pragma unroll
                for (int tp = 0; tp < 8; tp++) {
                    u32 boff = (u32)(((k16 * 16 + lr + lb8 * 8) * STB
                                    + tp * 16 + lb16 * 8) * 2);
                    u32 bh[4];
                    ldsm4t(bh[0], bh[1], bh[2], bh[3], sBhi + boff);
                    mma16816(acc[2 * tp],     ah, bh);
                    mma16816(acc[2 * tp],     al, bh);
                    mma16816(acc[2 * tp + 1], ah, bh + 2);
                    mma16816(acc[2 * tp + 1], al, bh + 2);
                }
            }
        }
        // epilogue: t<8 -> K (hi only), t>=8 -> V (hi only)
#pragma unroll
        for (int t = 0; t < 16; t++) {
            int row = m0 + wid * 16 + g;
            int col = (t & 7) * 8 + pp * 2;
            hf* Dhi = (t < 8) ? g_khi : g_vhi;
            *(u32*)(Dhi + (size_t)row * HS + col)       = cvt2(acc[t][0], acc[t][1]);
            *(u32*)(Dhi + (size_t)(row + 8) * HS + col) = cvt2(acc[t][2], acc[t][3]);
        }
    }
}

// =============================================================================
// Flash attention: one 64-row q-tile per CTA, 256 CTAs, 128 threads, 2 CTAs/SM.
// K/V hi-only, double-buffered via cp.async — ONE barrier per k-iteration.
// 2-pass fp16: GEMM1 (q_hi+q_lo)*k_hi, GEMM2 (p_hi+p_lo)*v_hi.
// Balanced bid->(qt,batch): co-resident pairs (bid, bid+148) sum to 28;
// the 40 solo SMs get the heaviest tiles (qt 27..31).
// =============================================================================
#define A_QHI 0
#define A_QLO 9216
#define A_KV0 18432         // per-buffer: khi +0, vhi +9216
#define A_KVSZ 18432
#define A_PHI 55296
#define A_PLO 64512
#define A_SMEM 73728

__global__ __launch_bounds__(128, 2)
void attn_kernel(float* __restrict__ out)
{
    extern __shared__ char dsm[];
    const u32 smb = smem_u32(dsm);
    hf* Qhi = (hf*)(dsm + A_QHI); hf* Qlo = (hf*)(dsm + A_QLO);
    hf* Phi = (hf*)(dsm + A_PHI); hf* Plo = (hf*)(dsm + A_PLO);
    const u32 sQhi = smb + A_QHI, sQlo = smb + A_QLO;
    const u32 sPhi = smb + A_PHI, sPlo = smb + A_PLO;

    const int tid = threadIdx.x, wid = tid >> 5, l = tid & 31;
    const int g = l >> 2, pp = l & 3;
    const int lr = l & 7, lb8 = (l >> 3) & 1, lb16 = l >> 4;

    // --- balanced bid -> (qt, batch) mapping ---
    int bid = blockIdx.x, qt, b;
    if (bid >= 108 && bid < 148) {
        int i = bid - 108;               // 40 solo-heavy tiles: qt 31..27
        qt = 31 - (i >> 3); b = i & 7;
    } else {
        int p = (bid < 108) ? bid : (bid - 148);
        bool second = (bid >= 148);
        if (p < 104) { int j = p >> 3; b = p & 7; qt = second ? (26 - j) : j; }
        else         { int q = p - 104; qt = 13; b = second ? (2 * q + 1) : (2 * q); }
    }
    const int q0 = qt * 64;

    const hf* QgH = g_qhi + (size_t)b * TSEQ * HS;
    const hf* QgL = g_qlo + (size_t)b * TSEQ * HS;
    const hf* KgH = g_khi + (size_t)b * TSEQ * HS;
    const hf* VgH = g_vhi + (size_t)b * TSEQ * HS;

    // Q tile: straight fp16 copy (8 uint4 / thread)
#pragma unroll
    for (int i = 0; i < 8; i++) {
        int idx = tid + 128 * i;
        int arr = idx >> 9, rem = idx & 511;
        int r = rem >> 3, seg = rem & 7;
        const hf* src = (arr ? QgL : QgH) + (size_t)(q0 + r) * HS + seg * 8;
        hf* dst = (arr ? Qlo : Qhi) + r * ST + seg * 8;
        *(uint4*)dst = *(const uint4*)src;
    }
    // prologue: cp.async K/V(hi) for kt=0 into buffer 0 (8 / thread)
#pragma unroll
    for (int i = 0; i < 8; i++) {
        int idx = tid + 128 * i;
        int arr = idx >> 9, rem = idx & 511;
        int r = rem >> 3, seg = rem & 7;
        const hf* src = (arr ? VgH : KgH) + (size_t)r * HS + seg * 8;
        cpa16(smb + A_KV0 + arr * 9216 + (r * ST + seg * 8) * 2, src);
    }
    cpa_commit();
    __syncthreads();

    // hoist Q a-frags
    u32 qh[4][4], ql[4][4];
#pragma unroll
    for (int k16 = 0; k16 < 4; k16++) {
        u32 off = (u32)(((wid * 16 + lr + lb8 * 8) * ST + k16 * 16 + lb16 * 8) * 2);
        ldsm4(qh[k16][0], qh[k16][1], qh[k16][2], qh[k16][3], sQhi + off);
        ldsm4(ql[k16][0], ql[k16][1], ql[k16][2], ql[k16][3], sQlo + off);
    }

    float o[8][4];
#pragma unroll
    for (int t = 0; t < 8; t++)
#pragma unroll
        for (int i = 0; i < 4; i++) o[t][i] = 0.f;
    float mrow[2] = {-1e30f, -1e30f};
    float lrow[2] = {0.f, 0.f};

    for (int kt = 0; kt <= qt; kt++) {
        const int cur = kt & 1;
        cpa_wait0();
        __syncthreads();   // K/V(kt) visible; all warps done with buffer cur^1

        if (kt < qt) {
            const int k0n = (kt + 1) * 64;
            const u32 dst0 = smb + A_KV0 + (cur ^ 1) * A_KVSZ;
#pragma unroll
            for (int i = 0; i < 8; i++) {
                int idx = tid + 128 * i;
                int arr = idx >> 9, rem = idx & 511;
                int r = rem >> 3, seg = rem & 7;
                const hf* src = (arr ? VgH : KgH) + (size_t)(k0n + r) * HS + seg * 8;
                cpa16(dst0 + arr * 9216 + (r * ST + seg * 8) * 2, src);
            }
            cpa_commit();
        }

        const u32 base = smb + A_KV0 + cur * A_KVSZ;
        const u32 sKhi = base, sVhi = base + 9216;
        const int k0 = kt * 64;

        // ---- GEMM1: S = Q K^T ----
        float s[8][4];
#pragma unroll
        for (int t = 0; t < 8; t++)
#pragma unroll
            for (int i = 0; i < 4; i++) s[t][i] = 0.f;
#pragma unroll
        for (int k16 = 0; k16 < 4; k16++) {
#pragma unroll
            for (int tp = 0; tp < 4; tp++) {
                u32 off = (u32)(((16 * tp + lr + lb16 * 8) * ST + k16 * 16 + lb8 * 8) * 2);
                u32 bh[4];
                ldsm4(bh[0], bh[1], bh[2], bh[3], sKhi + off);
                mma16816(s[2 * tp],     qh[k16], bh);
                mma16816(s[2 * tp],     ql[k16], bh);
                mma16816(s[2 * tp + 1], qh[k16], bh + 2);
                mma16816(s[2 * tp + 1], ql[k16], bh + 2);
            }
        }

        // ---- scale + causal mask ----
#pragma unroll
        for (int t = 0; t < 8; t++)
#pragma unroll
            for (int i = 0; i < 4; i++) s[t][i] *= 0.03125f;   // 1024^-0.5
        if (kt == qt) {
            const int r0 = q0 + wid * 16 + g, r1 = r0 + 8;
#pragma unroll
            for (int t = 0; t < 8; t++) {
                int c0 = k0 + t * 8 + pp * 2;
                if (c0 > r0)     s[t][0] = -1e30f;
                if (c0 + 1 > r0) s[t][1] = -1e30f;
                if (c0 > r1)     s[t][2] = -1e30f;
                if (c0 + 1 > r1) s[t][3] = -1e30f;
            }
        }

        // ---- online softmax ----
        float rmx[2] = {-1e30f, -1e30f};
#pragma unroll
        for (int t = 0; t < 8; t++) {
            rmx[0] = fmaxf(rmx[0], fmaxf(s[t][0], s[t][1]));
            rmx[1] = fmaxf(rmx[1], fmaxf(s[t][2], s[t][3]));
        }
        float scl[2], rs[2] = {0.f, 0.f};
#pragma unroll
        for (int r = 0; r < 2; r++) {
            rmx[r] = fmaxf(rmx[r], __shfl_xor_sync(0xffffffffu, rmx[r], 1));
            rmx[r] = fmaxf(rmx[r], __shfl_xor_sync(0xffffffffu, rmx[r], 2));
            float mn = fmaxf(mrow[r], rmx[r]);
            scl[r] = __expf(mrow[r] - mn);
            mrow[r] = mn;
        }
#pragma unroll
        for (int t = 0; t < 8; t++) {
            float p00 = __expf(s[t][0] - mrow[0]);
            float p01 = __expf(s[t][1] - mrow[0]);
            float p10 = __expf(s[t][2] - mrow[1]);
            float p11 = __expf(s[t][3] - mrow[1]);
            rs[0] += p00 + p01;
            rs[1] += p10 + p11;
            u32 hi, lo;
            split2(p00, p01, hi, lo);
            *(u32*)(Phi + (wid * 16 + g) * ST + t * 8 + pp * 2) = hi;
            *(u32*)(Plo + (wid * 16 + g) * ST + t * 8 + pp * 2) = lo;
            split2(p10, p11, hi, lo);
            *(u32*)(Phi + (wid * 16 + g + 8) * ST + t * 8 + pp * 2) = hi;
            *(u32*)(Plo + (wid * 16 + g + 8) * ST + t * 8 + pp * 2) = lo;
        }
#pragma unroll
        for (int r = 0; r < 2; r++) {
            rs[r] += __shfl_xor_sync(0xffffffffu, rs[r], 1);
            rs[r] += __shfl_xor_sync(0xffffffffu, rs[r], 2);
            lrow[r] = lrow[r] * scl[r] + rs[r];
        }
#pragma unroll
        for (int t = 0; t < 8; t++) {
            o[t][0] *= scl[0]; o[t][1] *= scl[0];
            o[t][2] *= scl[1]; o[t][3] *= scl[1];
        }
        __syncwarp();   // P writes are warp-local (rows wid*16..wid*16+15)

        // ---- GEMM2: O += P V  (V b-frags via ldmatrix.trans on [s][h]) ----
#pragma unroll
        for (int c16 = 0; c16 < 4; c16++) {
            u32 aoff = (u32)(((wid * 16 + lr + lb8 * 8) * ST + c16 * 16 + lb16 * 8) * 2);
            u32 ph[4], pl[4];
            ldsm4(ph[0], ph[1], ph[2], ph[3], sPhi + aoff);
            ldsm4(pl[0], pl[1], pl[2], pl[3], sPlo + aoff);
#pragma unroll
            for (int tp = 0; tp < 4; tp++) {
                u32 voff = (u32)(((c16 * 16 + lr + lb8 * 8) * ST + 16 * tp + lb16 * 8) * 2);
                u32 vh[4];
                ldsm4t(vh[0], vh[1], vh[2], vh[3], sVhi + voff);
                mma16816(o[2 * tp],     ph, vh);
                mma16816(o[2 * tp],     pl, vh);
                mma16816(o[2 * tp + 1], ph, vh + 2);
                mma16816(o[2 * tp + 1], pl, vh + 2);
            }
        }
    } // kt

    // ---- epilogue ----
    const float inv0 = 1.f / lrow[0], inv1 = 1.f / lrow[1];
    float* Og = out + ((size_t)b * TSEQ + q0) * HS;
#pragma unroll
    for (int t = 0; t < 8; t++) {
        int row = wid * 16 + g, col = t * 8 + pp * 2;
        *(float2*)(Og + (size_t)row * HS + col) =
            make_float2(o[t][0] * inv0, o[t][1] * inv0);
        *(float2*)(Og + (size_t)(row + 8) * HS + col) =
            make_float2(o[t][2] * inv1, o[t][3] * inv1);
    }
}

// =============================================================================
extern "C" void kernel_launch(void* const* d_in, const int* in_sizes, int n_in,
                              void* d_out, int out_size)
{
    const float* xq  = (const float*)d_in[0];
    const float* xkv = (const float*)d_in[1];
    const float* Wq  = (const float*)d_in[2];
    const float* Wk  = (const float*)d_in[3];
    const float* Wv  = (const float*)d_in[4];
    float* out = (float*)d_out;

    cudaFuncSetAttribute(proj_kernel, cudaFuncAttributeMaxDynamicSharedMemorySize, P_SMEM);
    cudaFuncSetAttribute(attn_kernel, cudaFuncAttributeMaxDynamicSharedMemorySize, A_SMEM);

    wsplit_kernel<<<192, 256>>>(Wq, Wk, Wv);
    proj_kernel<<<384, 128, P_SMEM>>>(xq, xkv);
    attn_kernel<<<256, 128, A_SMEM>>>(out);
}